// round 2
// baseline (speedup 1.0000x reference)
#include <cuda_runtime.h>

// LSTM2: 2-layer LSTM, B=1024, T=1024, H=64, input dim 1, output dim 1/step.
// Persistent-RNN design: 128 CTAs x 256 threads, 8 batch rows per CTA.
// All weights resident in SMEM (padded, conflict-free), cell state in registers,
// h double-buffered in SMEM (2 barriers/step), f32x2 packed FMAs (FFMA2).

namespace {

constexpr int T_LEN = 1024;
constexpr int BATCH = 1024;
constexpr int RPC   = 8;            // batch rows per CTA
constexpr int NTH   = 256;          // threads per CTA
constexpr int WPAD  = 68;           // padded row length (floats) for W and h
constexpr int HROW  = 68;
constexpr int HBUF  = RPC * HROW;   // 544 floats per h buffer
constexpr int GRID  = BATCH / RPC;  // 128

// floats of dynamic smem:
// 3 weight matrices (256x68) + 2 bias vecs (256) + w_ih1 (256) + w_lin (64)
// + h1,h2 double buffers (2*544 each) + x staging (16)
constexpr int SMEM_FLOATS = 3 * 256 * WPAD + 256 + 256 + 256 + 64 + 4 * HBUF + 16;
constexpr int SMEM_BYTES  = SMEM_FLOATS * 4;  // 220992 B

typedef unsigned long long u64;

__device__ __forceinline__ u64 fma2(u64 a, u64 b, u64 c) {
    u64 d;
    asm("fma.rn.f32x2 %0, %1, %2, %3;" : "=l"(d) : "l"(a), "l"(b), "l"(c));
    return d;
}
__device__ __forceinline__ float red2(u64 a) {
    return __uint_as_float((unsigned)a) + __uint_as_float((unsigned)(a >> 32));
}
__device__ __forceinline__ float sigm(float v) {
    return __fdividef(1.f, 1.f + __expf(-v));
}
__device__ __forceinline__ float tanh_(float v) {
    v = fminf(fmaxf(v, -15.f), 15.f);   // avoid inf/inf NaN; tanh saturated anyway
    float e = __expf(-2.f * v);
    return __fdividef(1.f - e, 1.f + e);
}

} // namespace

__global__ void __launch_bounds__(NTH, 1)
lstm2_kernel(const float* __restrict__ x,
             const float* __restrict__ w_ih1, const float* __restrict__ w_hh1,
             const float* __restrict__ b_ih1, const float* __restrict__ b_hh1,
             const float* __restrict__ w_ih2, const float* __restrict__ w_hh2,
             const float* __restrict__ b_ih2, const float* __restrict__ b_hh2,
             const float* __restrict__ w_lin, const float* __restrict__ b_lin,
             float* __restrict__ out)
{
    extern __shared__ float sm[];
    float* sWh1 = sm;                       // [256][68]  layer1 w_hh
    float* sWi2 = sWh1 + 256 * WPAD;        // [256][68]  layer2 w_ih
    float* sWh2 = sWi2 + 256 * WPAD;        // [256][68]  layer2 w_hh
    float* sB1  = sWh2 + 256 * WPAD;        // [256]  b_ih1+b_hh1
    float* sB2  = sB1 + 256;                // [256]
    float* sWx  = sB2 + 256;                // [256]  w_ih1 (input dim 1)
    float* sWl  = sWx + 256;                // [64]   w_lin
    float* sH1  = sWl + 64;                 // [2][8][68]
    float* sH2  = sH1 + 2 * HBUF;           // [2][8][68]
    float* sX   = sH2 + 2 * HBUF;           // [2][8]

    const int tid = threadIdx.x;
    const int rowbase = blockIdx.x * RPC;

    // ---- load weights into padded SMEM (once, reused for 1024 steps) ----
    for (int i = tid; i < 256 * 64; i += NTH) {
        int j = i >> 6, k = i & 63;
        sWh1[j * WPAD + k] = w_hh1[i];
        sWi2[j * WPAD + k] = w_ih2[i];
        sWh2[j * WPAD + k] = w_hh2[i];
    }
    sB1[tid] = b_ih1[tid] + b_hh1[tid];
    sB2[tid] = b_ih2[tid] + b_hh2[tid];
    sWx[tid] = w_ih1[tid];
    if (tid < 64) sWl[tid] = w_lin[tid];
    for (int i = tid; i < 2 * HBUF; i += NTH) { sH1[i] = 0.f; sH2[i] = 0.f; }
    if (tid < RPC) sX[tid] = x[(rowbase + tid) * T_LEN];   // x at t=0, buffer 0
    __syncthreads();

    // thread (rp, n): hidden unit n, rows r0=2rp, r1=2rp+1
    const int rp = tid & 3;
    const int n  = tid >> 2;
    const int r0 = rp * 2, r1 = r0 + 1;
    const int wid = tid >> 5, lid = tid & 31;

    const float b1i = sB1[n], b1f = sB1[n + 64], b1g = sB1[n + 128], b1o = sB1[n + 192];
    const float b2i = sB2[n], b2f = sB2[n + 64], b2g = sB2[n + 128], b2o = sB2[n + 192];
    const float wxi = sWx[n], wxf = sWx[n + 64], wxg = sWx[n + 128], wxo = sWx[n + 192];
    const float blin = b_lin[0];

    const ulonglong2* Wi = (const ulonglong2*)(sWh1 + n * WPAD);
    const ulonglong2* Wf = (const ulonglong2*)(sWh1 + (n + 64) * WPAD);
    const ulonglong2* Wg = (const ulonglong2*)(sWh1 + (n + 128) * WPAD);
    const ulonglong2* Wo = (const ulonglong2*)(sWh1 + (n + 192) * WPAD);
    const ulonglong2* Ui = (const ulonglong2*)(sWi2 + n * WPAD);
    const ulonglong2* Uf = (const ulonglong2*)(sWi2 + (n + 64) * WPAD);
    const ulonglong2* Ug = (const ulonglong2*)(sWi2 + (n + 128) * WPAD);
    const ulonglong2* Uo = (const ulonglong2*)(sWi2 + (n + 192) * WPAD);
    const ulonglong2* Vi = (const ulonglong2*)(sWh2 + n * WPAD);
    const ulonglong2* Vf = (const ulonglong2*)(sWh2 + (n + 64) * WPAD);
    const ulonglong2* Vg = (const ulonglong2*)(sWh2 + (n + 128) * WPAD);
    const ulonglong2* Vo = (const ulonglong2*)(sWh2 + (n + 192) * WPAD);

    // persistent cell state (registers)
    float c1a = 0.f, c1b = 0.f, c2a = 0.f, c2b = 0.f;

    for (int t = 0; t < T_LEN; ++t) {
        const int p = t & 1, q = p ^ 1;

        // prefetch next step's x (hidden under compute)
        float xn = 0.f;
        if (tid < RPC) {
            int tn = (t + 1 < T_LEN) ? (t + 1) : t;
            xn = x[(rowbase + tid) * T_LEN + tn];
        }
        const float xa = sX[p * RPC + r0];
        const float xb = sX[p * RPC + r1];

        // ================= layer 1: gates over h1[p] =================
        {
            const ulonglong2* Ha = (const ulonglong2*)(sH1 + p * HBUF + r0 * HROW);
            const ulonglong2* Hb = (const ulonglong2*)(sH1 + p * HBUF + r1 * HROW);
            u64 ai0 = 0, af0 = 0, ag0 = 0, ao0 = 0;
            u64 ai1 = 0, af1 = 0, ag1 = 0, ao1 = 0;
            #pragma unroll
            for (int k = 0; k < 16; ++k) {
                ulonglong2 ha = Ha[k], hb = Hb[k];
                ulonglong2 wi = Wi[k], wf = Wf[k], wg = Wg[k], wo = Wo[k];
                ai0 = fma2(wi.x, ha.x, ai0); ai0 = fma2(wi.y, ha.y, ai0);
                af0 = fma2(wf.x, ha.x, af0); af0 = fma2(wf.y, ha.y, af0);
                ag0 = fma2(wg.x, ha.x, ag0); ag0 = fma2(wg.y, ha.y, ag0);
                ao0 = fma2(wo.x, ha.x, ao0); ao0 = fma2(wo.y, ha.y, ao0);
                ai1 = fma2(wi.x, hb.x, ai1); ai1 = fma2(wi.y, hb.y, ai1);
                af1 = fma2(wf.x, hb.x, af1); af1 = fma2(wf.y, hb.y, af1);
                ag1 = fma2(wg.x, hb.x, ag1); ag1 = fma2(wg.y, hb.y, ag1);
                ao1 = fma2(wo.x, hb.x, ao1); ao1 = fma2(wo.y, hb.y, ao1);
            }
            // row r0
            float gi = b1i + wxi * xa + red2(ai0);
            float gf = b1f + wxf * xa + red2(af0);
            float gg = b1g + wxg * xa + red2(ag0);
            float go = b1o + wxo * xa + red2(ao0);
            float ii = sigm(gi), ff = sigm(gf), gc = tanh_(gg), oo = sigm(go);
            c1a = ff * c1a + ii * gc;
            float h1a = oo * tanh_(c1a);
            // row r1
            gi = b1i + wxi * xb + red2(ai1);
            gf = b1f + wxf * xb + red2(af1);
            gg = b1g + wxg * xb + red2(ag1);
            go = b1o + wxo * xb + red2(ao1);
            ii = sigm(gi); ff = sigm(gf); gc = tanh_(gg); oo = sigm(go);
            c1b = ff * c1b + ii * gc;
            float h1b = oo * tanh_(c1b);

            sH1[q * HBUF + r0 * HROW + n] = h1a;
            sH1[q * HBUF + r1 * HROW + n] = h1b;
        }
        if (tid < RPC) sX[q * RPC + tid] = xn;
        __syncthreads();   // b1: h1[q] + x[q] published

        // ====== layer 2: gates over h1[q] (new) and h2[p] (old) ======
        {
            const ulonglong2* Pa = (const ulonglong2*)(sH1 + q * HBUF + r0 * HROW);
            const ulonglong2* Pb = (const ulonglong2*)(sH1 + q * HBUF + r1 * HROW);
            const ulonglong2* Qa = (const ulonglong2*)(sH2 + p * HBUF + r0 * HROW);
            const ulonglong2* Qb = (const ulonglong2*)(sH2 + p * HBUF + r1 * HROW);
            u64 ai0 = 0, af0 = 0, ag0 = 0, ao0 = 0;
            u64 ai1 = 0, af1 = 0, ag1 = 0, ao1 = 0;
            #pragma unroll
            for (int k = 0; k < 16; ++k) {
                ulonglong2 pa = Pa[k], pb = Pb[k], qa = Qa[k], qb = Qb[k];
                ulonglong2 ui = Ui[k], uf = Uf[k], ug = Ug[k], uo = Uo[k];
                ulonglong2 vi = Vi[k], vf = Vf[k], vg = Vg[k], vo = Vo[k];
                ai0 = fma2(ui.x, pa.x, ai0); ai0 = fma2(ui.y, pa.y, ai0);
                ai0 = fma2(vi.x, qa.x, ai0); ai0 = fma2(vi.y, qa.y, ai0);
                af0 = fma2(uf.x, pa.x, af0); af0 = fma2(uf.y, pa.y, af0);
                af0 = fma2(vf.x, qa.x, af0); af0 = fma2(vf.y, qa.y, af0);
                ag0 = fma2(ug.x, pa.x, ag0); ag0 = fma2(ug.y, pa.y, ag0);
                ag0 = fma2(vg.x, qa.x, ag0); ag0 = fma2(vg.y, qa.y, ag0);
                ao0 = fma2(uo.x, pa.x, ao0); ao0 = fma2(uo.y, pa.y, ao0);
                ao0 = fma2(vo.x, qa.x, ao0); ao0 = fma2(vo.y, qa.y, ao0);
                ai1 = fma2(ui.x, pb.x, ai1); ai1 = fma2(ui.y, pb.y, ai1);
                ai1 = fma2(vi.x, qb.x, ai1); ai1 = fma2(vi.y, qb.y, ai1);
                af1 = fma2(uf.x, pb.x, af1); af1 = fma2(uf.y, pb.y, af1);
                af1 = fma2(vf.x, qb.x, af1); af1 = fma2(vf.y, qb.y, af1);
                ag1 = fma2(ug.x, pb.x, ag1); ag1 = fma2(ug.y, pb.y, ag1);
                ag1 = fma2(vg.x, qb.x, ag1); ag1 = fma2(vg.y, qb.y, ag1);
                ao1 = fma2(uo.x, pb.x, ao1); ao1 = fma2(uo.y, pb.y, ao1);
                ao1 = fma2(vo.x, qb.x, ao1); ao1 = fma2(vo.y, qb.y, ao1);
            }
            // row r0
            float gi = b2i + red2(ai0);
            float gf = b2f + red2(af0);
            float gg = b2g + red2(ag0);
            float go = b2o + red2(ao0);
            float ii = sigm(gi), ff = sigm(gf), gc = tanh_(gg), oo = sigm(go);
            c2a = ff * c2a + ii * gc;
            float h2a = oo * tanh_(c2a);
            // row r1
            gi = b2i + red2(ai1);
            gf = b2f + red2(af1);
            gg = b2g + red2(ag1);
            go = b2o + red2(ao1);
            ii = sigm(gi); ff = sigm(gf); gc = tanh_(gg); oo = sigm(go);
            c2b = ff * c2b + ii * gc;
            float h2b = oo * tanh_(c2b);

            sH2[q * HBUF + r0 * HROW + n] = h2a;
            sH2[q * HBUF + r1 * HROW + n] = h2b;
        }
        __syncthreads();   // b2: h2[q] published

        // ====== output: warp w reduces row w of h2[q] against w_lin ======
        {
            const float* hr = sH2 + q * HBUF + wid * HROW;
            float v = hr[lid] * sWl[lid] + hr[lid + 32] * sWl[lid + 32];
            #pragma unroll
            for (int off = 16; off; off >>= 1)
                v += __shfl_xor_sync(0xffffffffu, v, off);
            if (lid == 0) out[(rowbase + wid) * T_LEN + t] = v + blin;
        }
    }
}

extern "C" void kernel_launch(void* const* d_in, const int* in_sizes, int n_in,
                              void* d_out, int out_size)
{
    const float* x     = (const float*)d_in[0];
    const float* w_ih1 = (const float*)d_in[1];
    const float* w_hh1 = (const float*)d_in[2];
    const float* b_ih1 = (const float*)d_in[3];
    const float* b_hh1 = (const float*)d_in[4];
    const float* w_ih2 = (const float*)d_in[5];
    const float* w_hh2 = (const float*)d_in[6];
    const float* b_ih2 = (const float*)d_in[7];
    const float* b_hh2 = (const float*)d_in[8];
    const float* w_lin = (const float*)d_in[9];
    const float* b_lin = (const float*)d_in[10];
    // d_in[11] = future_preds (0 for this problem)

    cudaFuncSetAttribute(lstm2_kernel,
                         cudaFuncAttributeMaxDynamicSharedMemorySize, SMEM_BYTES);

    lstm2_kernel<<<GRID, NTH, SMEM_BYTES>>>(
        x, w_ih1, w_hh1, b_ih1, b_hh1,
        w_ih2, w_hh2, b_ih2, b_hh2,
        w_lin, b_lin, (float*)d_out);
}